// round 16
// baseline (speedup 1.0000x reference)
#include <cuda_runtime.h>
#include <math.h>

#define SCALE 0.08838834764831845f  // 1/sqrt(128)
#define NB 384
#define NT 256

typedef unsigned long long ull;

// ---------------- f32x2 packed helpers (sm_100a) ----------------
__device__ __forceinline__ ull pk(float lo, float hi) {
    ull r;
    asm("mov.b64 %0,{%1,%2};" : "=l"(r) : "f"(lo), "f"(hi));
    return r;
}
__device__ __forceinline__ float2 upk(ull v) {
    float2 r;
    asm("mov.b64 {%0,%1},%2;" : "=f"(r.x), "=f"(r.y) : "l"(v));
    return r;
}
__device__ __forceinline__ void fma2(ull& d, ull a, ull b) {
    asm("fma.rn.f32x2 %0,%1,%2,%0;" : "+l"(d) : "l"(a), "l"(b));
}
__device__ __forceinline__ void add2(ull& d, ull a) {
    asm("add.rn.f32x2 %0,%1,%0;" : "+l"(d) : "l"(a));
}

// ---------------- sync state (epoch-based; graph-replay safe) ----------------
__device__ unsigned g_count;
__device__ volatile unsigned g_release;
__device__ unsigned g_ctA;
__device__ volatile unsigned g_relA;
__device__ unsigned g_ctB;
__device__ volatile unsigned g_relB;
__device__ unsigned g_task;
__device__ float g_dummy;

// ---------------- scratch ----------------
__device__ __align__(16) float g_hl[512];
__device__ __align__(16) float g_qpart[16][512];
__device__ __align__(16) float g_gs[4][512];
__device__ __align__(16) float g_cpart[64][12];
__device__ __align__(16) float g_C[12];
__device__ __align__(16) float g_pm[16][32][4];
__device__ __align__(16) float g_pse[16][32][4];
__device__ __align__(16) float g_pewb[16][32][4];
__device__ __align__(16) float g_ppart[16][32][4][512];
__device__ __align__(16) float g_ctxpart[32][32][512];
__device__ __align__(16) float g_h1[32][512];
__device__ __align__(16) float g_w1part[8][32][2048];

// warp reduction via shfl tree (redux.sync.add.f32 NOT supported on sm_100)
static __device__ __forceinline__ float wred(float v) {
#pragma unroll
    for (int o = 16; o; o >>= 1) v += __shfl_xor_sync(0xffffffffu, v, o);
    return v;
}

static __device__ __forceinline__ float geluf(float t) {
    float t3 = t * t * t;
    return 0.5f * t * (1.f + tanhf(0.7978845608028654f * (t + 0.044715f * t3)));
}

__device__ __forceinline__ void gridbar(unsigned base, unsigned idx) {
    __syncthreads();
    if (threadIdx.x == 0) {
        __threadfence();
        if (atomicAdd(&g_count, 1u) == NB - 1) {
            g_count = 0;
            __threadfence();
            g_release = base + idx;
        } else {
            while ((unsigned)(g_release - base) < idx) __nanosleep(32);
            __threadfence();
        }
    }
    __syncthreads();
}

__global__ void __launch_bounds__(NT, 3) fused_kernel(
    const float* __restrict__ x, const int* __restrict__ mask,
    const float* __restrict__ token,
    const float* __restrict__ Wq, const float* __restrict__ bq,
    const float* __restrict__ Wk,
    const float* __restrict__ Wv, const float* __restrict__ bv,
    const float* __restrict__ Wo, const float* __restrict__ bo,
    const float* __restrict__ s1, const float* __restrict__ b1,
    const float* __restrict__ s2, const float* __restrict__ b2l,
    const float* __restrict__ W1, const float* __restrict__ b1f,
    const float* __restrict__ W2, const float* __restrict__ b2o,
    float* __restrict__ out) {
    __shared__ float SM[3072];
    __shared__ unsigned s_base_sh;
    __shared__ int s_last;
    __shared__ int s_task[2];
    int tid = threadIdx.x;
    int bid = blockIdx.x;
    int wid = tid >> 5, lane = tid & 31;
    if (tid == 0) s_base_sh = g_release;
    __syncthreads();
    unsigned base = s_base_sh;

    // ================= PHASE I: prologue (flag-synced) + split task loop =================
    if (bid < 16) {
        // --- token LN + q partials ---
        float t0 = token[tid], t1 = token[tid + 256];
        float* red = SM;
        red[tid] = t0 + t1;
        __syncthreads();
#pragma unroll
        for (int o = 128; o; o >>= 1) {
            if (tid < o) red[tid] += red[tid + o];
            __syncthreads();
        }
        float mean = red[0] * (1.f / 512.f);
        __syncthreads();
        float d0 = t0 - mean, d1 = t1 - mean;
        red[tid] = d0 * d0 + d1 * d1;
        __syncthreads();
#pragma unroll
        for (int o = 128; o; o >>= 1) {
            if (tid < o) red[tid] += red[tid + o];
            __syncthreads();
        }
        float rstd = rsqrtf(red[0] * (1.f / 512.f) + 1e-5f);
        __syncthreads();
        float* shl = SM;
        float hl0 = d0 * rstd * s1[tid] + b1[tid];
        float hl1 = d1 * rstd * s1[tid + 256] + b1[tid + 256];
        shl[tid] = hl0;
        shl[tid + 256] = hl1;
        if (bid == 0) {
            g_hl[tid] = hl0;
            g_hl[tid + 256] = hl1;
        }
        __syncthreads();
        int j0 = bid * 32;
        float a0 = 0.f, a1 = 0.f;
#pragma unroll
        for (int j = 0; j < 32; j++) {
            float h = shl[j0 + j];
            a0 = fmaf(h, Wq[(size_t)(j0 + j) * 512 + tid], a0);
            a1 = fmaf(h, Wq[(size_t)(j0 + j) * 512 + tid + 256], a1);
        }
        g_qpart[bid][tid] = a0;
        g_qpart[bid][tid + 256] = a1;
        __threadfence();
        __syncthreads();
        if (tid == 0) {
            if (atomicAdd(&g_ctA, 1u) == 15) {
                g_ctA = 0;
                __threadfence();
                g_relA = base + 1;
            }
        }
        // --- prefetch weights into L2 ---
        {
            int pw = bid * 256 + tid;
            float acc = 0.f;
            const float4* a1p = (const float4*)Wv;
            const float4* a2p = (const float4*)Wo;
            const float4* a3p = (const float4*)W1;
            const float4* a4p = (const float4*)W2;
#pragma unroll 2
            for (int i = pw; i < 65536; i += 20480) acc += __ldg(a1p + i).x + __ldg(a2p + i).x;
#pragma unroll 4
            for (int i = pw; i < 262144; i += 20480) acc += __ldg(a3p + i).x + __ldg(a4p + i).x;
            if (acc == 1.2345e30f) g_dummy = acc;
        }
    } else if (bid < 80) {
        // --- wait q partials ---
        if (tid == 0) {
            while ((unsigned)(g_relA - base) < 1u) __nanosleep(32);
            __threadfence();
        }
        __syncthreads();
        // --- combine q; gs rows; C partials ---
        float* sq = SM;
        float q0 = bq[tid], q1 = bq[tid + 256];
#pragma unroll
        for (int s = 0; s < 16; s++) {
            q0 += g_qpart[s][tid];
            q1 += g_qpart[s][tid + 256];
        }
        sq[tid] = q0;
        sq[tid + 256] = q1;
        __syncthreads();
        int r = (bid - 16) * 8 + wid;
        const float4* wr = (const float4*)(Wk + (size_t)r * 512);
        const float4* q4 = (const float4*)sq;
        float dt[4];
#pragma unroll
        for (int t = 0; t < 4; t++) {
            float4 w = __ldg(wr + lane + 32 * t);
            float4 q = q4[lane + 32 * t];
            dt[t] = w.x * q.x + w.y * q.y + w.z * q.z + w.w * q.w;
        }
#pragma unroll
        for (int t = 0; t < 4; t++) dt[t] = wred(dt[t]);
        float* cred = SM + 512;  // [8][12]
        if (lane == 0) {
            float sr = s1[r], br = b1[r], hr = g_hl[r];
#pragma unroll
            for (int t = 0; t < 4; t++) {
                g_gs[t][r] = dt[t] * sr;
                cred[wid * 12 + t] = sr * dt[t];
                cred[wid * 12 + 4 + t] = br * dt[t];
                cred[wid * 12 + 8 + t] = hr * dt[t];
            }
        }
        __syncthreads();
        if (tid < 12) {
            float c = 0.f;
#pragma unroll
            for (int w = 0; w < 8; w++) c += cred[w * 12 + tid];
            g_cpart[bid - 16][tid] = c;
        }
        __threadfence();
        __syncthreads();
        if (tid == 0) s_last = (atomicAdd(&g_ctB, 1u) == 63) ? 1 : 0;
        __syncthreads();
        if (s_last) {
            if (tid < 12) {
                float c = 0.f;
#pragma unroll
                for (int j = 0; j < 64; j++) c += g_cpart[j][tid];
                g_C[tid] = c;
            }
            __threadfence();
            __syncthreads();
            if (tid == 0) {
                g_ctB = 0;
                __threadfence();
                g_relB = base + 1;
            }
        }
        // --- prefetch weights ---
        {
            int pw = bid * 256 + tid;
            float acc = 0.f;
            const float4* a1p = (const float4*)Wv;
            const float4* a2p = (const float4*)Wo;
            const float4* a3p = (const float4*)W1;
            const float4* a4p = (const float4*)W2;
#pragma unroll 2
            for (int i = pw; i < 65536; i += 20480) acc += __ldg(a1p + i).x + __ldg(a2p + i).x;
#pragma unroll 4
            for (int i = pw; i < 262144; i += 20480) acc += __ldg(a3p + i).x + __ldg(a4p + i).x;
            if (acc == 1.2345e30f) g_dummy = acc;
        }
    } else {
        // --- prefetch x into L2 while prologue runs (2-row batches, MLP 8) ---
        int pw = (bid - 80) * 8 + wid;  // 0..2431
        float acc = 0.f;
        for (int rr = pw; rr < 8192; rr += 2432) {
            int r = rr * 2;
            int bA = r >> 9, kA = r & 511;
            int L = __ldg(&mask[bA]);
            bool vA = kA < L, vB = (kA + 1) < L;
            const float4* xr = (const float4*)(x + (size_t)r * 512);
            if (vA) {
#pragma unroll
                for (int t = 0; t < 4; t++) acc += __ldg(xr + lane + 32 * t).x;
            }
            if (vB) {
#pragma unroll
                for (int t = 0; t < 4; t++) acc += __ldg(xr + 128 + lane + 32 * t).x;
            }
        }
        if (acc == 1.2345e30f) g_dummy = acc;
    }
    // --- all blocks: wait gs/C ready ---
    if (tid == 0) {
        while ((unsigned)(g_relB - base) < 1u) __nanosleep(32);
        __threadfence();
    }
    __syncthreads();
    // --- load gs + C to smem ---
    for (int i = tid; i < 2048; i += NT) SM[i] = ((const float*)g_gs)[i];
    if (tid < 12) SM[2048 + tid] = g_C[tid];
    __syncthreads();
    {
        const ulonglong2* sgs2 = (const ulonglong2*)SM;
        float C1[4], C2[4];
#pragma unroll
        for (int h = 0; h < 4; h++) {
            C1[h] = SM[2048 + h];
            C2[h] = SM[2052 + h];
        }
        int half = tid >> 7, t128 = tid & 127, w = t128 >> 5;
        float* sS = SM + 2064 + half * 464;  // sc[128], al[32], be[32], w[128], e[128]
        int nbar = 1 + half;
        // ---- task loop: each task = one (b, ks) split, processed end-to-end ----
        while (true) {
            if (t128 == 0) s_task[half] = (int)atomicAdd(&g_task, 1u);
            asm volatile("bar.sync %0, 128;" ::"r"(nbar));
            int t = s_task[half];
            if (t >= 512) break;
            int ks = t & 15, b = t >> 4;
            int L = __ldg(&mask[b]);
            int k0 = ks * 32;
            if (k0 >= L) {
                // empty split: fs=exp(-1e30-M)=0 zeroes any stale g_ppart contribution
                if (t128 < 4) {
                    g_pm[ks][b][t128] = -1e30f;
                    g_pse[ks][b][t128] = 0.f;
                    g_pewb[ks][b][t128] = 0.f;
                }
                continue;
            }
            // --- score pass: each warp 8 single rows; stats inline; f32x2 packed ---
#pragma unroll 1
            for (int it = 0; it < 8; it++) {
                int kl = w * 8 + it;
                int kg = k0 + kl;
                bool v0 = kg < L;  // warp-uniform
                if (!v0) {
                    if (lane == 0) {
#pragma unroll
                        for (int h = 0; h < 4; h++) sS[kl * 4 + h] = -1e30f;
                        sS[128 + kl] = 0.f;
                        sS[160 + kl] = 0.f;
                    }
                    continue;
                }
                const ulonglong2* xr0 = (const ulonglong2*)(x + ((size_t)b * 512 + kg) * 512);
                ulonglong2 xa[4];
#pragma unroll
                for (int tt = 0; tt < 4; tt++) xa[tt] = __ldg(xr0 + lane + 32 * tt);
                ull ssA2 = 0ull, smA2 = 0ull;
#pragma unroll
                for (int tt = 0; tt < 4; tt++) {
                    fma2(ssA2, xa[tt].x, xa[tt].x);
                    fma2(ssA2, xa[tt].y, xa[tt].y);
                    add2(smA2, xa[tt].x);
                    add2(smA2, xa[tt].y);
                }
                ull dA2[4] = {0ull, 0ull, 0ull, 0ull};
#pragma unroll
                for (int h = 0; h < 4; h++) {
#pragma unroll
                    for (int tt = 0; tt < 4; tt++) {
                        ulonglong2 g = sgs2[h * 128 + lane + 32 * tt];
                        fma2(dA2[h], xa[tt].x, g.x);
                        fma2(dA2[h], xa[tt].y, g.y);
                    }
                }
                float dA[4];
#pragma unroll
                for (int h = 0; h < 4; h++) {
                    float2 pa = upk(dA2[h]);
                    dA[h] = wred(pa.x + pa.y);
                }
                float2 u;
                u = upk(ssA2);
                float ssA = wred(u.x + u.y);
                u = upk(smA2);
                float smA = wred(u.x + u.y);
                if (lane == 0) {
                    float inv = 1.f / fmaxf(sqrtf(ssA), 1e-12f);
                    float m = smA * inv * (1.f / 512.f);
                    float v = ssA * inv * inv * (1.f / 512.f) - m * m;
                    float rs = rsqrtf(v + 1e-5f);
                    float al0 = inv * rs, be0 = -m * rs;
#pragma unroll
                    for (int h = 0; h < 4; h++)
                        sS[kl * 4 + h] = SCALE * (al0 * dA[h] + be0 * C1[h] + C2[h]);
                    sS[128 + kl] = al0;
                    sS[160 + kl] = be0;
                }
            }
            asm volatile("bar.sync %0, 128;" ::"r"(nbar));
            // --- e/w compute: thread (k,h) ---
            {
                int k = t128 >> 2, h = t128 & 3;
                float m = -1e30f;
#pragma unroll 8
                for (int j = 0; j < 32; j++) m = fmaxf(m, sS[j * 4 + h]);
                float e = __expf(sS[k * 4 + h] - m);
                sS[320 + k * 4 + h] = e;
                sS[192 + k * 4 + h] = e * sS[128 + k];
                if (k == 0) g_pm[ks][b][h] = m;
            }
            asm volatile("bar.sync %0, 128;" ::"r"(nbar));
            // --- A accumulate (x rows warm in L1), f32x2 packed ---
            int kv = L - k0;
            kv = kv > 32 ? 32 : kv;
            ull A0a = 0ull, A0b = 0ull, A1a = 0ull, A1b = 0ull;
            ull A2a = 0ull, A2b = 0ull, A3a = 0ull, A3b = 0ull;
            const ulonglong2* xb2 = (const ulonglong2*)(x + ((size_t)b * 512 + k0) * 512);
#pragma unroll 4
            for (int k = 0; k < kv; k++) {
                float4 w4 = *(const float4*)&sS[192 + k * 4];
                ull wx = pk(w4.x, w4.x), wy = pk(w4.y, w4.y);
                ull wz = pk(w4.z, w4.z), ww = pk(w4.w, w4.w);
                ulonglong2 xv = __ldg(xb2 + (size_t)k * 128 + t128);
                fma2(A0a, wx, xv.x);
                fma2(A0b, wx, xv.y);
                fma2(A1a, wy, xv.x);
                fma2(A1b, wy, xv.y);
                fma2(A2a, wz, xv.x);
                fma2(A2b, wz, xv.y);
                fma2(A3a, ww, xv.x);
                fma2(A3b, ww, xv.y);
            }
            int i = t128 * 4;
            {
                ulonglong2 st;
                st.x = A0a; st.y = A0b;
                *(ulonglong2*)&g_ppart[ks][b][0][i] = st;
                st.x = A1a; st.y = A1b;
                *(ulonglong2*)&g_ppart[ks][b][1][i] = st;
                st.x = A2a; st.y = A2b;
                *(ulonglong2*)&g_ppart[ks][b][2][i] = st;
                st.x = A3a; st.y = A3b;
                *(ulonglong2*)&g_ppart[ks][b][3][i] = st;
            }
            if (t128 < 4) {
                float se = 0.f, ewb = 0.f;
#pragma unroll 8
                for (int k = 0; k < 32; k++) {
                    float e = sS[320 + k * 4 + t128];
                    se += e;
                    ewb += e * sS[160 + k];
                }
                g_pse[ks][b][t128] = se;
                g_pewb[ks][b][t128] = ewb;
            }
            asm volatile("bar.sync %0, 128;" ::"r"(nbar));
        }
    }
    // ---- barrier 1 (leader also resets task counter) ----
    __syncthreads();
    if (tid == 0) {
        __threadfence();
        if (atomicAdd(&g_count, 1u) == NB - 1) {
            g_count = 0;
            g_task = 0;
            __threadfence();
            g_release = base + 1;
        } else {
            while ((unsigned)(g_release - base) < 1u) __nanosleep(32);
            __threadfence();
        }
    }
    __syncthreads();

    // ============ T1': init h1; combine scalars + rescale + p @ Wv (512 vblocks) ============
    if (bid < 256) {
        // init h1 = token + bo (finalized by T2's atomics)
        if (tid < 64) {
            int idx = bid * 64 + tid;
            g_h1[idx >> 9][idx & 511] = token[idx & 511] + bo[idx & 511];
        }
        int half = tid >> 7, t128 = tid & 127;
        int vb = bid * 2 + half;
        int bh = vb & 3, hh = (vb >> 2) & 3, iy = vb >> 4;  // iy 0..31
        int i0 = iy * 16, f = hh * 128 + t128;
        float* sb = SM + half * 160;
        float* sp = SM + 320 + half * 128;
        if (t128 < 8) {
            int gb = bh * 8 + t128;
            float scls = SCALE * g_C[8 + hh];
            float M = scls;
#pragma unroll
            for (int s = 0; s < 16; s++) M = fmaxf(M, g_pm[s][gb][hh]);
            float Se = 0.f, Ewb = 0.f;
#pragma unroll
            for (int s = 0; s < 16; s++) {
                float fs = __expf(g_pm[s][gb][hh] - M);
                sb[t128 * 16 + s] = fs;
                Se += fs * g_pse[s][gb][hh];
                Ewb += fs * g_pewb[s][gb][hh];
            }
            float ecls = __expf(scls - M);
            sb[128 + t128] = 1.f / (Se + ecls);
            sb[136 + t128] = Se;
            sb[144 + t128] = Ewb;
            sb[152 + t128] = ecls;
        }
        __syncthreads();
        {
            int bl = t128 >> 4, ii = t128 & 15;
            int gb = bh * 8 + bl;
            int i = i0 + ii;
            float A = 0.f;
#pragma unroll
            for (int s = 0; s < 16; s++) A = fmaf(sb[bl * 16 + s], g_ppart[s][gb][hh][i], A);
            sp[t128] = sb[128 + bl] *
                       (s1[i] * (A + sb[144 + bl]) + b1[i] * sb[136 + bl] + sb[152 + bl] * g_hl[i]);
        }
        __syncthreads();
        float acc[8];
#pragma unroll
        for (int bl = 0; bl < 8; bl++) acc[bl] = 0.f;
#pragma unroll
        for (int ii = 0; ii < 16; ii += 4) {
            int i = i0 + ii;
            float w0 = Wv[(size_t)i * 512 + f];
            float w1 = Wv[(size_t)(i + 1) * 512 + f];
            float w2 = Wv[(size_t)(i + 2) * 512 + f];
            float w3 = Wv[(size_t)(i + 3) * 512 + f];
#pragma unroll
            for (int bl = 0; bl < 8; bl++) {
                float4 p = *(const float4*)&sp[bl * 16 + ii];
                acc[bl] = fmaf(p.x, w0, fmaf(p.y, w1, fmaf(p.z, w2, fmaf(p.w, w3, acc[bl]))));
            }
        }
#pragma unroll
        for (int bl = 0; bl < 8; bl++) g_ctxpart[iy][bh * 8 + bl][f] = acc[bl];
    }
    gridbar(base, 2);

    // ============ T2: o = (ctx+bv) @ Wo, atomic-accumulate into h1 (512 vblocks) ============
    if (bid < 256) {
        int half = tid >> 7, t128 = tid & 127;
        int vb = bid * 2 + half;
        int bh = vb & 3, cx = (vb >> 2) & 3, iy = vb >> 4;
        int i0 = iy * 16, f = cx * 128 + t128;
        float* sc = SM + half * 128;
        {
            int bl = t128 >> 4, ii = t128 & 15;
            int gb = bh * 8 + bl;
            int i = i0 + ii;
            float v = bv[i];
#pragma unroll
            for (int s = 0; s < 32; s++) v += g_ctxpart[s][gb][i];
            sc[t128] = v;
        }
        __syncthreads();
        float acc[8];
#pragma unroll
        for (int bl = 0; bl < 8; bl++) acc[bl] = 0.f;
#pragma unroll
        for (int ii = 0; ii < 16; ii += 4) {
            int i = i0 + ii;
            float w0 = Wo[(size_t)i * 512 + f];
            float w1 = Wo[(size_t)(i + 1) * 512 + f];
            float w2 = Wo[(size_t)(i + 2) * 512 + f];
            float w3 = Wo[(size_t)(i + 3) * 512 + f];
#pragma unroll
            for (int bl = 0; bl < 8; bl++) {
                float4 p = *(const float4*)&sc[bl * 16 + ii];
                acc[bl] = fmaf(p.x, w0, fmaf(p.y, w1, fmaf(p.z, w2, fmaf(p.w, w3, acc[bl]))));
            }
        }
#pragma unroll
        for (int bl = 0; bl < 8; bl++) atomicAdd(&g_h1[bh * 8 + bl][f], acc[bl]);
    }
    gridbar(base, 3);

    // ============ T4: inline LN2 stats + W1 partials (512 vblocks); init out ============
    if (bid < 256) {
        // init out = h1 + b2o (h1 final after barrier 3)
        if (tid < 64) {
            int idx = bid * 64 + tid;
            out[idx] = g_h1[idx >> 9][idx & 511] + b2o[idx & 511];
        }
        int half = tid >> 7, t128 = tid & 127;
        int vb = bid * 2 + half;  // 0..511
        int fx = vb & 15, bh = (vb >> 4) & 3, iy = vb >> 6;  // iy 0..7
        int i0 = iy * 64, f = fx * 128 + t128;
        float* sh2 = SM + half * 512;        // [8 b][64 i]
        float* sln = SM + 1024 + half * 16;  // [8 b][2]
        // inline LN2 stats (16 threads per batch)
        {
            int bl = t128 >> 4, sub = t128 & 15;
            int b = bh * 8 + bl;
            const float4* hb = (const float4*)g_h1[b];
            float sum = 0.f, ssq = 0.f;
#pragma unroll
            for (int j = 0; j < 8; j++) {
                float4 v = hb[sub * 8 + j];
                sum += v.x + v.y + v.z + v.w;
                ssq += v.x * v.x + v.y * v.y + v.z * v.z + v.w * v.w;
            }
#pragma unroll
            for (int o = 8; o; o >>= 1) {
                sum += __shfl_xor_sync(0xffffffffu, sum, o);
                ssq += __shfl_xor_sync(0xffffffffu, ssq, o);
            }
            if (sub == 0) {
                float m = sum * (1.f / 512.f);
                float var = ssq * (1.f / 512.f) - m * m;
                sln[bl * 2] = m;
                sln[bl * 2 + 1] = rsqrtf(var + 1e-5f);
            }
        }
        __syncthreads();
#pragma unroll
        for (int j = 0; j < 4; j++) {
            int idx = t128 + j * 128;
            int bl = idx >> 6, ii = idx & 63;
            int b = bh * 8 + bl, i = i0 + ii;
            sh2[idx] = (g_h1[b][i] - sln[bl * 2]) * sln[bl * 2 + 1] * s2[i] + b2l[i];
        }
        __syncthreads();
        float acc[8];
#pragma unroll
        for (int bl = 0; bl < 8; bl++) acc[bl] = 0.f;
#pragma unroll 4
        for (int ii = 0; ii < 64; ii += 4) {
            int i = i0 + ii;
            float w0 = W1[(size_t)i * 2048 + f];
            float w1 = W1[(size_t)(i + 1) * 2048 + f];
            float w2 = W1[(size_t)(i + 2) * 2048 + f];
            float w3 = W1[(size_t)(i + 3) * 2048 + f];
#pragma unroll
            for (int bl = 0; bl < 8; bl++) {
                float4 p = *(const float4*)&sh2[bl * 64 + ii];
                acc[bl] = fmaf(p.x, w0, fmaf(p.y, w1, fmaf(p.z, w2, fmaf(p.w, w3, acc[bl]))));
            }
        }
#pragma unroll
        for (int bl = 0; bl < 8; bl++) g_w1part[iy][bh * 8 + bl][f] = acc[bl];
    }
    gridbar(base, 4);

    // ============ T5: gelu + W2, atomic-accumulate into out (512 vblocks) ============
    if (bid < 256) {
        int half = tid >> 7, t128 = tid & 127;
        int vb = bid * 2 + half;  // 0..511
        int fx = vb & 3, bh = (vb >> 2) & 7, iy = vb >> 5;  // iy 0..15
        int i0 = iy * 128, f = fx * 128 + t128;
        float* su = SM + half * 512;  // [4 b][128 i]
        {
#pragma unroll
            for (int j = 0; j < 4; j++) {
                int idx = t128 + j * 128;
                int bl = idx >> 7, ii = idx & 127;
                int b = bh * 4 + bl, i = i0 + ii;
                float u = b1f[i];
#pragma unroll
                for (int s = 0; s < 8; s++) u += g_w1part[s][b][i];
                su[idx] = geluf(u);
            }
        }
        __syncthreads();
        float acc[4];
#pragma unroll
        for (int bl = 0; bl < 4; bl++) acc[bl] = 0.f;
#pragma unroll 4
        for (int ii = 0; ii < 128; ii += 4) {
            int i = i0 + ii;
            float w0 = W2[(size_t)i * 512 + f];
            float w1 = W2[(size_t)(i + 1) * 512 + f];
            float w2 = W2[(size_t)(i + 2) * 512 + f];
            float w3 = W2[(size_t)(i + 3) * 512 + f];
#pragma unroll
            for (int bl = 0; bl < 4; bl++) {
                float4 p = *(const float4*)&su[bl * 128 + ii];
                acc[bl] = fmaf(p.x, w0, fmaf(p.y, w1, fmaf(p.z, w2, fmaf(p.w, w3, acc[bl]))));
            }
        }
#pragma unroll
        for (int bl = 0; bl < 4; bl++) atomicAdd(&out[(bh * 4 + bl) * 512 + f], acc[bl]);
    }
}

extern "C" void kernel_launch(void* const* d_in, const int* in_sizes, int n_in,
                              void* d_out, int out_size) {
    const float* x     = (const float*)d_in[0];
    const int*   mask  = (const int*)d_in[1];
    const float* token = (const float*)d_in[2];
    const float* Wq    = (const float*)d_in[3];
    const float* bq    = (const float*)d_in[4];
    const float* Wk    = (const float*)d_in[5];
    // d_in[6] = bk: uniform shift across keys -> cancels in softmax; unused
    const float* Wv    = (const float*)d_in[7];
    const float* bv    = (const float*)d_in[8];
    const float* Wo    = (const float*)d_in[9];
    const float* bo    = (const float*)d_in[10];
    const float* s1    = (const float*)d_in[11];
    const float* b1    = (const float*)d_in[12];
    const float* s2    = (const float*)d_in[13];
    const float* b2l   = (const float*)d_in[14];
    const float* W1    = (const float*)d_in[15];
    const float* b1f   = (const float*)d_in[16];
    const float* W2    = (const float*)d_in[17];
    const float* b2o   = (const float*)d_in[18];
    float* out = (float*)d_out;

    fused_kernel<<<NB, NT>>>(x, mask, token, Wq, bq, Wk, Wv, bv, Wo, bo,
                             s1, b1, s2, b2l, W1, b1f, W2, b2o, out);
}

// round 17
// speedup vs baseline: 1.0048x; 1.0048x over previous
#include <cuda_runtime.h>
#include <math.h>

#define SCALE 0.08838834764831845f  // 1/sqrt(128)
#define NB 256
#define NT 256

typedef unsigned long long ull;

// ---------------- f32x2 packed helpers (sm_100a) ----------------
__device__ __forceinline__ ull pk(float lo, float hi) {
    ull r;
    asm("mov.b64 %0,{%1,%2};" : "=l"(r) : "f"(lo), "f"(hi));
    return r;
}
__device__ __forceinline__ float2 upk(ull v) {
    float2 r;
    asm("mov.b64 {%0,%1},%2;" : "=f"(r.x), "=f"(r.y) : "l"(v));
    return r;
}
__device__ __forceinline__ void fma2(ull& d, ull a, ull b) {
    asm("fma.rn.f32x2 %0,%1,%2,%0;" : "+l"(d) : "l"(a), "l"(b));
}
__device__ __forceinline__ void add2(ull& d, ull a) {
    asm("add.rn.f32x2 %0,%1,%0;" : "+l"(d) : "l"(a));
}

// ---------------- sync state (epoch-based; graph-replay safe) ----------------
__device__ unsigned g_count;
__device__ volatile unsigned g_release;
__device__ unsigned g_ctA;
__device__ volatile unsigned g_relA;
__device__ unsigned g_ctB;
__device__ volatile unsigned g_relB;
__device__ unsigned g_task;
__device__ float g_dummy;

// ---------------- scratch ----------------
__device__ __align__(16) float g_hl[512];
__device__ __align__(16) float g_qpart[16][512];
__device__ __align__(16) float g_gs[4][512];
__device__ __align__(16) float g_cpart[64][12];
__device__ __align__(16) float g_C[12];
__device__ __align__(16) float g_pm[16][32][4];
__device__ __align__(16) float g_pse[16][32][4];
__device__ __align__(16) float g_pewb[16][32][4];
__device__ __align__(16) float g_ppart[16][32][4][512];
__device__ __align__(16) float g_ctxpart[32][32][512];
__device__ __align__(16) float g_h1[32][512];
__device__ __align__(16) float g_w1part[8][32][2048];

// warp reduction via shfl tree (redux.sync.add.f32 NOT supported on sm_100)
static __device__ __forceinline__ float wred(float v) {
#pragma unroll
    for (int o = 16; o; o >>= 1) v += __shfl_xor_sync(0xffffffffu, v, o);
    return v;
}

static __device__ __forceinline__ float geluf(float t) {
    float t3 = t * t * t;
    return 0.5f * t * (1.f + tanhf(0.7978845608028654f * (t + 0.044715f * t3)));
}

__device__ __forceinline__ void gridbar(unsigned base, unsigned idx) {
    __syncthreads();
    if (threadIdx.x == 0) {
        __threadfence();
        if (atomicAdd(&g_count, 1u) == NB - 1) {
            g_count = 0;
            __threadfence();
            g_release = base + idx;
        } else {
            while ((unsigned)(g_release - base) < idx) __nanosleep(32);
            __threadfence();
        }
    }
    __syncthreads();
}

__global__ void __launch_bounds__(NT, 2) fused_kernel(
    const float* __restrict__ x, const int* __restrict__ mask,
    const float* __restrict__ token,
    const float* __restrict__ Wq, const float* __restrict__ bq,
    const float* __restrict__ Wk,
    const float* __restrict__ Wv, const float* __restrict__ bv,
    const float* __restrict__ Wo, const float* __restrict__ bo,
    const float* __restrict__ s1, const float* __restrict__ b1,
    const float* __restrict__ s2, const float* __restrict__ b2l,
    const float* __restrict__ W1, const float* __restrict__ b1f,
    const float* __restrict__ W2, const float* __restrict__ b2o,
    float* __restrict__ out) {
    __shared__ float SM[3072];
    __shared__ unsigned s_base_sh;
    __shared__ int s_last;
    __shared__ int s_task[2];
    int tid = threadIdx.x;
    int bid = blockIdx.x;
    int wid = tid >> 5, lane = tid & 31;
    if (tid == 0) s_base_sh = g_release;
    __syncthreads();
    unsigned base = s_base_sh;

    // ================= PHASE I: prologue (flag-synced) + split task loop =================
    if (bid < 16) {
        // --- prefetch this block's Wq slice (64KB) into L2 BEFORE the LN chain ---
        {
            const char* wq = (const char*)(Wq + (size_t)bid * 32 * 512);
#pragma unroll
            for (int j = 0; j < 2; j++)
                asm volatile("prefetch.global.L2 [%0];" ::"l"(wq + (tid + j * 256) * 128));
        }
        // --- token LN + q partials ---
        float t0 = token[tid], t1 = token[tid + 256];
        float* red = SM;
        red[tid] = t0 + t1;
        __syncthreads();
#pragma unroll
        for (int o = 128; o; o >>= 1) {
            if (tid < o) red[tid] += red[tid + o];
            __syncthreads();
        }
        float mean = red[0] * (1.f / 512.f);
        __syncthreads();
        float d0 = t0 - mean, d1 = t1 - mean;
        red[tid] = d0 * d0 + d1 * d1;
        __syncthreads();
#pragma unroll
        for (int o = 128; o; o >>= 1) {
            if (tid < o) red[tid] += red[tid + o];
            __syncthreads();
        }
        float rstd = rsqrtf(red[0] * (1.f / 512.f) + 1e-5f);
        __syncthreads();
        float* shl = SM;
        float hl0 = d0 * rstd * s1[tid] + b1[tid];
        float hl1 = d1 * rstd * s1[tid + 256] + b1[tid + 256];
        shl[tid] = hl0;
        shl[tid + 256] = hl1;
        if (bid == 0) {
            g_hl[tid] = hl0;
            g_hl[tid + 256] = hl1;
        }
        __syncthreads();
        int j0 = bid * 32;
        float a0 = 0.f, a1 = 0.f;
#pragma unroll
        for (int j = 0; j < 32; j++) {
            float h = shl[j0 + j];
            a0 = fmaf(h, Wq[(size_t)(j0 + j) * 512 + tid], a0);
            a1 = fmaf(h, Wq[(size_t)(j0 + j) * 512 + tid + 256], a1);
        }
        g_qpart[bid][tid] = a0;
        g_qpart[bid][tid + 256] = a1;
        __threadfence();
        __syncthreads();
        if (tid == 0) {
            if (atomicAdd(&g_ctA, 1u) == 15) {
                g_ctA = 0;
                __threadfence();
                g_relA = base + 1;
            }
        }
        // --- prefetch weights into L2 ---
        {
            int pw = bid * 256 + tid;
            float acc = 0.f;
            const float4* a1p = (const float4*)Wv;
            const float4* a2p = (const float4*)Wo;
            const float4* a3p = (const float4*)W1;
            const float4* a4p = (const float4*)W2;
#pragma unroll 2
            for (int i = pw; i < 65536; i += 20480) acc += __ldg(a1p + i).x + __ldg(a2p + i).x;
#pragma unroll 4
            for (int i = pw; i < 262144; i += 20480) acc += __ldg(a3p + i).x + __ldg(a4p + i).x;
            if (acc == 1.2345e30f) g_dummy = acc;
        }
    } else if (bid < 80) {
        // --- hoist Wk row load BEFORE the flagA wait (cold DRAM fetch overlaps q compute) ---
        int r = (bid - 16) * 8 + wid;
        const float4* wr = (const float4*)(Wk + (size_t)r * 512);
        float4 wv4[4];
#pragma unroll
        for (int t = 0; t < 4; t++) wv4[t] = __ldg(wr + lane + 32 * t);
        // --- wait q partials ---
        if (tid == 0) {
            while ((unsigned)(g_relA - base) < 1u) __nanosleep(32);
            __threadfence();
        }
        __syncthreads();
        // --- combine q; gs rows; C partials ---
        float* sq = SM;
        float q0 = bq[tid], q1 = bq[tid + 256];
#pragma unroll
        for (int s = 0; s < 16; s++) {
            q0 += g_qpart[s][tid];
            q1 += g_qpart[s][tid + 256];
        }
        sq[tid] = q0;
        sq[tid + 256] = q1;
        __syncthreads();
        const float4* q4 = (const float4*)sq;
        float dt[4];
#pragma unroll
        for (int t = 0; t < 4; t++) {
            float4 q = q4[lane + 32 * t];
            dt[t] = wv4[t].x * q.x + wv4[t].y * q.y + wv4[t].z * q.z + wv4[t].w * q.w;
        }
#pragma unroll
        for (int t = 0; t < 4; t++) dt[t] = wred(dt[t]);
        float* cred = SM + 512;  // [8][12]
        if (lane == 0) {
            float sr = s1[r], br = b1[r], hr = g_hl[r];
#pragma unroll
            for (int t = 0; t < 4; t++) {
                g_gs[t][r] = dt[t] * sr;
                cred[wid * 12 + t] = sr * dt[t];
                cred[wid * 12 + 4 + t] = br * dt[t];
                cred[wid * 12 + 8 + t] = hr * dt[t];
            }
        }
        __syncthreads();
        if (tid < 12) {
            float c = 0.f;
#pragma unroll
            for (int w = 0; w < 8; w++) c += cred[w * 12 + tid];
            g_cpart[bid - 16][tid] = c;
        }
        __threadfence();
        __syncthreads();
        if (tid == 0) s_last = (atomicAdd(&g_ctB, 1u) == 63) ? 1 : 0;
        __syncthreads();
        if (s_last) {
            if (tid < 12) {
                float c = 0.f;
#pragma unroll
                for (int j = 0; j < 64; j++) c += g_cpart[j][tid];
                g_C[tid] = c;
            }
            __threadfence();
            __syncthreads();
            if (tid == 0) {
                g_ctB = 0;
                __threadfence();
                g_relB = base + 1;
            }
        }
        // --- prefetch weights ---
        {
            int pw = bid * 256 + tid;
            float acc = 0.f;
            const float4* a1p = (const float4*)Wv;
            const float4* a2p = (const float4*)Wo;
            const float4* a3p = (const float4*)W1;
            const float4* a4p = (const float4*)W2;
#pragma unroll 2
            for (int i = pw; i < 65536; i += 20480) acc += __ldg(a1p + i).x + __ldg(a2p + i).x;
#pragma unroll 4
            for (int i = pw; i < 262144; i += 20480) acc += __ldg(a3p + i).x + __ldg(a4p + i).x;
            if (acc == 1.2345e30f) g_dummy = acc;
        }
    } else {
        // --- prefetch x into L2 while prologue runs (2-row batches, MLP 8) ---
        int pw = (bid - 80) * 8 + wid;  // 0..1407
        float acc = 0.f;
        for (int rr = pw; rr < 8192; rr += 1408) {
            int r = rr * 2;
            int bA = r >> 9, kA = r & 511;
            int L = __ldg(&mask[bA]);
            bool vA = kA < L, vB = (kA + 1) < L;
            const float4* xr = (const float4*)(x + (size_t)r * 512);
            if (vA) {
#pragma unroll
                for (int t = 0; t < 4; t++) acc += __ldg(xr + lane + 32 * t).x;
            }
            if (vB) {
#pragma unroll
                for (int t = 0; t < 4; t++) acc += __ldg(xr + 128 + lane + 32 * t).x;
            }
        }
        if (acc == 1.2345e30f) g_dummy = acc;
    }
    // --- all blocks: wait gs/C ready ---
    if (tid == 0) {
        while ((unsigned)(g_relB - base) < 1u) __nanosleep(32);
        __threadfence();
    }
    __syncthreads();
    // --- load gs + C to smem ---
    for (int i = tid; i < 2048; i += NT) SM[i] = ((const float*)g_gs)[i];
    if (tid < 12) SM[2048 + tid] = g_C[tid];
    __syncthreads();
    {
        const ulonglong2* sgs2 = (const ulonglong2*)SM;
        float C1[4], C2[4];
#pragma unroll
        for (int h = 0; h < 4; h++) {
            C1[h] = SM[2048 + h];
            C2[h] = SM[2052 + h];
        }
        int half = tid >> 7, t128 = tid & 127, w = t128 >> 5;
        float* sS = SM + 2064 + half * 464;  // sc[128], al[32], be[32], w[128], e[128]
        int nbar = 1 + half;
        // ---- task loop: each task = one (b, ks) split, processed end-to-end ----
        while (true) {
            if (t128 == 0) s_task[half] = (int)atomicAdd(&g_task, 1u);
            asm volatile("bar.sync %0, 128;" ::"r"(nbar));
            int t = s_task[half];
            if (t >= 512) break;
            int ks = t & 15, b = t >> 4;
            int L = __ldg(&mask[b]);
            int k0 = ks * 32;
            if (k0 >= L) {
                // empty split: fs=exp(-1e30-M)=0 zeroes any stale g_ppart contribution
                if (t128 < 4) {
                    g_pm[ks][b][t128] = -1e30f;
                    g_pse[ks][b][t128] = 0.f;
                    g_pewb[ks][b][t128] = 0.f;
                }
                continue;
            }
            // --- score pass: each warp 8 rows, 2-batched; stats inline; f32x2 packed ---
#pragma unroll 1
            for (int it = 0; it < 4; it++) {
                int kl = w * 8 + it * 2;
                int kg = k0 + kl;
                bool v0 = kg < L, v1 = kg + 1 < L;  // warp-uniform
                if (!v0) {
                    if (lane == 0) {
#pragma unroll
                        for (int h = 0; h < 4; h++) {
                            sS[kl * 4 + h] = -1e30f;
                            sS[(kl + 1) * 4 + h] = -1e30f;
                        }
                        sS[128 + kl] = 0.f;
                        sS[128 + kl + 1] = 0.f;
                        sS[160 + kl] = 0.f;
                        sS[160 + kl + 1] = 0.f;
                    }
                    continue;
                }
                const ulonglong2* xr0 = (const ulonglong2*)(x + ((size_t)b * 512 + kg) * 512);
                ulonglong2 xa[4], xc[4];
#pragma unroll
                for (int tt = 0; tt < 4; tt++) xa[tt] = __ldg(xr0 + lane + 32 * tt);
                if (v1) {
#pragma unroll
                    for (int tt = 0; tt < 4; tt++) xc[tt] = __ldg(xr0 + 128 + lane + 32 * tt);
                }
                // row A reductions
                ull ssA2 = 0ull, smA2 = 0ull;
#pragma unroll
                for (int tt = 0; tt < 4; tt++) {
                    fma2(ssA2, xa[tt].x, xa[tt].x);
                    fma2(ssA2, xa[tt].y, xa[tt].y);
                    add2(smA2, xa[tt].x);
                    add2(smA2, xa[tt].y);
                }
                ull dA2[4] = {0ull, 0ull, 0ull, 0ull};
#pragma unroll
                for (int h = 0; h < 4; h++) {
#pragma unroll
                    for (int tt = 0; tt < 4; tt++) {
                        ulonglong2 g = sgs2[h * 128 + lane + 32 * tt];
                        fma2(dA2[h], xa[tt].x, g.x);
                        fma2(dA2[h], xa[tt].y, g.y);
                    }
                }
                float dA[4];
#pragma unroll
                for (int h = 0; h < 4; h++) {
                    float2 pa = upk(dA2[h]);
                    dA[h] = wred(pa.x + pa.y);
                }
                float2 u;
                u = upk(ssA2);
                float ssA = wred(u.x + u.y);
                u = upk(smA2);
                float smA = wred(u.x + u.y);
                // row B reductions (warp-uniform skip)
                float dB[4] = {0.f, 0.f, 0.f, 0.f};
                float ssB = 0.f, smB = 0.f;
                if (v1) {
                    ull ssB2 = 0ull, smB2 = 0ull;
#pragma unroll
                    for (int tt = 0; tt < 4; tt++) {
                        fma2(ssB2, xc[tt].x, xc[tt].x);
                        fma2(ssB2, xc[tt].y, xc[tt].y);
                        add2(smB2, xc[tt].x);
                        add2(smB2, xc[tt].y);
                    }
                    ull dB2[4] = {0ull, 0ull, 0ull, 0ull};
#pragma unroll
                    for (int h = 0; h < 4; h++) {
#pragma unroll
                        for (int tt = 0; tt < 4; tt++) {
                            ulonglong2 g = sgs2[h * 128 + lane + 32 * tt];
                            fma2(dB2[h], xc[tt].x, g.x);
                            fma2(dB2[h], xc[tt].y, g.y);
                        }
                    }
#pragma unroll
                    for (int h = 0; h < 4; h++) {
                        float2 pb = upk(dB2[h]);
                        dB[h] = wred(pb.x + pb.y);
                    }
                    u = upk(ssB2);
                    ssB = wred(u.x + u.y);
                    u = upk(smB2);
                    smB = wred(u.x + u.y);
                }
                if (lane == 0) {
                    float inv = 1.f / fmaxf(sqrtf(ssA), 1e-12f);
                    float m = smA * inv * (1.f / 512.f);
                    float v = ssA * inv * inv * (1.f / 512.f) - m * m;
                    float rs = rsqrtf(v + 1e-5f);
                    float al0 = inv * rs, be0 = -m * rs;
                    float al1 = 0.f, be1 = 0.f;
                    if (v1) {
                        inv = 1.f / fmaxf(sqrtf(ssB), 1e-12f);
                        m = smB * inv * (1.f / 512.f);
                        v = ssB * inv * inv * (1.f / 512.f) - m * m;
                        rs = rsqrtf(v + 1e-5f);
                        al1 = inv * rs;
                        be1 = -m * rs;
                    }
#pragma unroll
                    for (int h = 0; h < 4; h++) {
                        sS[kl * 4 + h] = SCALE * (al0 * dA[h] + be0 * C1[h] + C2[h]);
                        sS[(kl + 1) * 4 + h] =
                            v1 ? SCALE * (al1 * dB[h] + be1 * C1[h] + C2[h]) : -1e30f;
                    }
                    sS[128 + kl] = al0;
                    sS[128 + kl + 1] = al1;
                    sS[160 + kl] = be0;
                    sS[160 + kl + 1] = be1;
                }
            }
            asm volatile("bar.sync %0, 128;" ::"r"(nbar));
            // --- e/w compute: thread (k,h) ---
            {
                int k = t128 >> 2, h = t128 & 3;
                float m = -1e30f;
#pragma unroll 8
                for (int j = 0; j < 32; j++) m = fmaxf(m, sS[j * 4 + h]);
                float e = __expf(sS[k * 4 + h] - m);
                sS[320 + k * 4 + h] = e;
                sS[192 + k * 4 + h] = e * sS[128 + k];
                if (k == 0) g_pm[ks][b][h] = m;
            }
            asm volatile("bar.sync %0, 128;" ::"r"(nbar));
            // --- A accumulate (x rows warm in L1), f32x2 packed ---
            int kv = L - k0;
            kv = kv > 32 ? 32 : kv;
            ull A0a = 0ull, A0b = 0ull, A1a = 0ull, A1b = 0ull;
            ull A2a = 0ull, A2b = 0ull, A3a = 0ull, A3b = 0ull;
            const ulonglong2* xb2 = (const ulonglong2*)(x + ((size_t)b * 512 + k0) * 512);
#pragma unroll 4
            for (int k = 0; k < kv; k++) {
                float4 w4 = *(const float4*)&sS[192 + k * 4];
                ull wx = pk(w4.x, w4.x), wy = pk(w4.y, w4.y);
                ull wz = pk(w4.z, w4.z), ww = pk(w4.w, w4.w);
                ulonglong2 xv = __ldg(xb2 + (size_t)k * 128 + t128);
                fma2(A0a, wx, xv.x);
                fma2(A0b, wx, xv.y);
                fma2(A1a, wy, xv.x);
                fma2(A1b, wy, xv.y);
                fma2(A2a, wz, xv.x);
                fma2(A2b, wz, xv.y);
                fma2(A3a, ww, xv.x);
                fma2(A3b, ww, xv.y);
            }
            int i = t128 * 4;
            {
                ulonglong2 st;
                st.x = A0a; st.y = A0b;
                *(ulonglong2*)&g_ppart[ks][b][0][i] = st;
                st.x = A1a; st.y = A1b;
                *(ulonglong2*)&g_ppart[ks][b][1][i] = st;
                st.x = A2a; st.y = A2b;
                *(ulonglong2*)&g_ppart[ks][b][2][i] = st;
                st.x = A3a; st.y = A3b;
                *(ulonglong2*)&g_ppart[ks][b][3][i] = st;
            }
            if (t128 < 4) {
                float se = 0.f, ewb = 0.f;
#pragma unroll 8
                for (int k = 0; k < 32; k++) {
                    float e = sS[320 + k * 4 + t128];
                    se += e;
                    ewb += e * sS[160 + k];
                }
                g_pse[ks][b][t128] = se;
                g_pewb[ks][b][t128] = ewb;
            }
            asm volatile("bar.sync %0, 128;" ::"r"(nbar));
        }
    }
    // ---- barrier 1 (leader also resets task counter) ----
    __syncthreads();
    if (tid == 0) {
        __threadfence();
        if (atomicAdd(&g_count, 1u) == NB - 1) {
            g_count = 0;
            g_task = 0;
            __threadfence();
            g_release = base + 1;
        } else {
            while ((unsigned)(g_release - base) < 1u) __nanosleep(32);
            __threadfence();
        }
    }
    __syncthreads();

    // ============ T1': init h1; combine scalars + rescale + p @ Wv (512 vblocks) ============
    {
        // init h1 = token + bo (finalized by T2's atomics)
        if (tid < 64) {
            int idx = bid * 64 + tid;
            g_h1[idx >> 9][idx & 511] = token[idx & 511] + bo[idx & 511];
        }
        int half = tid >> 7, t128 = tid & 127;
        int vb = bid * 2 + half;
        int bh = vb & 3, hh = (vb >> 2) & 3, iy = vb >> 4;  // iy 0..31
        int i0 = iy * 16, f = hh * 128 + t128;
        float* sb = SM + half * 160;
        float* sp = SM + 320 + half * 128;
        if (t128 < 8) {
            int gb = bh * 8 + t128;
            float scls = SCALE * g_C[8 + hh];
            float ms[16];
            float M = scls;
#pragma unroll
            for (int s = 0; s < 16; s++) {
                ms[s] = g_pm[s][gb][hh];
                M = fmaxf(M, ms[s]);
            }
            float Se = 0.f, Ewb = 0.f;
#pragma unroll
            for (int s = 0; s < 16; s++) {
                float fs = __expf(ms[s] - M);
                sb[t128 * 16 + s] = fs;
                Se += fs * g_pse[s][gb][hh];
                Ewb += fs * g_pewb[s][gb][hh];
            }
            float ecls = __expf(scls - M);
            sb[128 + t128] = 1.f / (Se + ecls);
            sb[136 + t128] = Se;
            sb[144 + t128] = Ewb;
            sb[152 + t128] = ecls;
        }
        __syncthreads();
        {
            int bl = t128 >> 4, ii = t128 & 15;
            int gb = bh * 8 + bl;
            int i = i0 + ii;
            float A = 0.f;
#pragma unroll
            for (int s = 0; s < 16; s++) A = fmaf(sb[bl * 16 + s], g_ppart[s][gb][hh][i], A);
            sp[t128] = sb[128 + bl] *
                       (s1[i] * (A + sb[144 + bl]) + b1[i] * sb[136 + bl] + sb[152 + bl] * g_hl[i]);
        }
        __syncthreads();
        float acc[8];
#pragma unroll
        for (int bl = 0; bl < 8; bl++) acc[bl] = 0.f;
#pragma unroll
        for (int ii = 0; ii < 16; ii += 4) {
            int i = i0 + ii;
            float w0 = Wv[(size_t)i * 512 + f];
            float w1 = Wv[(size_t)(i + 1) * 512 + f];
            float w2 = Wv[(size_t)(i + 2) * 512 + f];
            float w3 = Wv[(size_t)(i + 3) * 512 + f];
#pragma unroll
            for (int bl = 0; bl < 8; bl++) {
                float4 p = *(const float4*)&sp[bl * 16 + ii];
                acc[bl] = fmaf(p.x, w0, fmaf(p.y, w1, fmaf(p.z, w2, fmaf(p.w, w3, acc[bl]))));
            }
        }
#pragma unroll
        for (int bl = 0; bl < 8; bl++) g_ctxpart[iy][bh * 8 + bl][f] = acc[bl];
    }
    gridbar(base, 2);

    // ============ T2: o = (ctx+bv) @ Wo, atomic-accumulate into h1 (512 vblocks) ============
    {
        int half = tid >> 7, t128 = tid & 127;
        int vb = bid * 2 + half;
        int bh = vb & 3, cx = (vb >> 2) & 3, iy = vb >> 4;
        int i0 = iy * 16, f = cx * 128 + t128;
        float* sc = SM + half * 128;
        {
            int bl = t128 >> 4, ii = t128 & 15;
            int gb = bh * 8 + bl;
            int i = i0 + ii;
            float v = bv[i];
#pragma unroll
            for (int s = 0; s < 32; s++) v += g_ctxpart[s][gb][i];
            sc[t128] = v;
        }
        __syncthreads();
        float acc[8];
#pragma unroll
        for (int bl = 0; bl < 8; bl++) acc[bl] = 0.f;
#pragma unroll
        for (int ii = 0; ii < 16; ii += 4) {
            int i = i0 + ii;
            float w0 = Wo[(size_t)i * 512 + f];
            float w1 = Wo[(size_t)(i + 1) * 512 + f];
            float w2 = Wo[(size_t)(i + 2) * 512 + f];
            float w3 = Wo[(size_t)(i + 3) * 512 + f];
#pragma unroll
            for (int bl = 0; bl < 8; bl++) {
                float4 p = *(const float4*)&sc[bl * 16 + ii];
                acc[bl] = fmaf(p.x, w0, fmaf(p.y, w1, fmaf(p.z, w2, fmaf(p.w, w3, acc[bl]))));
            }
        }
#pragma unroll
        for (int bl = 0; bl < 8; bl++) atomicAdd(&g_h1[bh * 8 + bl][f], acc[bl]);
    }
    gridbar(base, 3);

    // ============ T4: inline LN2 stats + W1 partials (512 vblocks); init out ============
    {
        // init out = h1 + b2o (h1 final after barrier 3)
        if (tid < 64) {
            int idx = bid * 64 + tid;
            out[idx] = g_h1[idx >> 9][idx & 511] + b2o[idx & 511];
        }
        int half = tid >> 7, t128 = tid & 127;
        int vb = bid * 2 + half;  // 0..511
        int fx = vb & 15, bh = (vb >> 4) & 3, iy = vb >> 6;  // iy 0..7
        int i0 = iy * 64, f = fx * 128 + t128;
        float* sh2 = SM + half * 512;        // [8 b][64 i]
        float* sln = SM + 1024 + half * 16;  // [8 b][2]
        // inline LN2 stats (16 threads per batch)
        {
            int bl = t128 >> 4, sub = t128 & 15;
            int b = bh * 8 + bl;
            const float4* hb = (const float4*)g_h1[b];
            float sum = 0.f, ssq = 0.f;
#pragma unroll
            for (int j = 0; j < 8; j++) {
                float4 v = hb[sub * 8 + j];
                sum += v.x + v.y + v.z + v.w;
                ssq += v.x * v.x + v.y * v.y + v.z * v.z + v.w * v.w;
            }
#pragma unroll
            for (int o = 8; o; o >>= 1) {
                sum += __shfl_xor_sync(0xffffffffu, sum, o);
                ssq += __shfl_xor_sync(0xffffffffu, ssq, o);
            }
            if (sub == 0) {
                float m = sum * (1.f / 512.f);
                float var = ssq * (1.f / 512.f) - m * m;
                sln[bl * 2] = m;
                sln[bl * 2 + 1] = rsqrtf(var + 1e-5f);
            }
        }
        __syncthreads();
#pragma unroll
        for (int j = 0; j < 4; j++) {
            int idx = t128 + j * 128;
            int bl = idx >> 6, ii = idx & 63;
            int b = bh * 8 + bl, i = i0 + ii;
            sh2[idx] = (g_h1[b][i] - sln[bl * 2]) * sln[bl * 2 + 1] * s2[i] + b2l[i];
        }
        __syncthreads();
        ull acc2[8];
#pragma unroll
        for (int bl = 0; bl < 8; bl++) acc2[bl] = 0ull;
#pragma unroll 4
        for (int ii = 0; ii < 64; ii += 4) {
            int i = i0 + ii;
            float w0 = W1[(size_t)i * 2048 + f];
            float w1 = W1[(size_t)(i + 1) * 2048 + f];
            float w2 = W1[(size_t)(i + 2) * 2048 + f];
            float w3 = W1[(size_t)(i + 3) * 2048 + f];
            ull w01 = pk(w0, w1), w23 = pk(w2, w3);
#pragma unroll
            for (int bl = 0; bl < 8; bl++) {
                const ull* pp = (const ull*)&sh2[bl * 64 + ii];
                fma2(acc2[bl], pp[0], w01);
                fma2(acc2[bl], pp[1], w23);
            }
        }
#pragma unroll
        for (int bl = 0; bl < 8; bl++) {
            float2 r = upk(acc2[bl]);
            g_w1part[iy][bh * 8 + bl][f] = r.x + r.y;
        }
    }
    gridbar(base, 4);

    // ============ T5: gelu + W2, atomic-accumulate into out (512 vblocks) ============
    {
        int half = tid >> 7, t128 = tid & 127;
        int vb = bid * 2 + half;  // 0..511
        int fx = vb & 3, bh = (vb >> 2) & 7, iy = vb >> 5;  // iy 0..15
        int i0 = iy * 128, f = fx * 128 + t128;
        float* su = SM + half * 512;  // [4 b][128 i]
        {
#pragma unroll
            for (int j = 0; j < 4; j++) {
                int idx = t128 + j * 128;
                int bl = idx >> 7, ii = idx & 127;
                int b = bh * 4 + bl, i = i0 + ii;
                float u = b1f[i];
#pragma unroll
                for (int s = 0; s < 8; s++) u += g_w1part[s][b][i];
                su[idx] = geluf(u);
            }
        }
        __syncthreads();
        ull acc2[4];
#pragma unroll
        for (int bl = 0; bl < 4; bl++) acc2[bl] = 0ull;
#pragma unroll 4
        for (int ii = 0; ii < 128; ii += 4) {
            int i = i0 + ii;
            float w0 = W2[(size_t)i * 512 + f];
            float w1 = W2[(size_t)(i + 1) * 512 + f];
            float w2 = W2[(size_t)(i + 2) * 512 + f];
            float w3 = W2[(size_t)(i + 3) * 512 + f];
            ull w01 = pk(w0, w1), w23 = pk(w2, w3);
#pragma unroll
            for (int bl = 0; bl < 4; bl++) {
                const ull* pp = (const ull*)&su[bl * 128 + ii];
                fma2(acc2[bl], pp[0], w01);
                fma2(acc2[bl], pp[1], w23);
            }
        }
#pragma unroll
        for (int bl = 0; bl < 4; bl++) {
            float2 r = upk(acc2[bl]);
            atomicAdd(&out[(bh * 4 + bl) * 512 + f], r.x + r.y);
        }
    }
}

extern "C" void kernel_launch(void* const* d_in, const int* in_sizes, int n_in,
                              void* d_out, int out_size) {
    const float* x     = (const float*)d_in[0];
    const int*   mask  = (const int*)d_in[1];
    const float* token = (const float*)d_in[2];
    const float* Wq    = (const float*)d_in[3];
    const float* bq    = (const float*)d_in[4];
    const float* Wk    = (const float*)d_in[5];
    // d_in[6] = bk: uniform shift across keys -> cancels in softmax; unused
    const float* Wv    = (const float*)d_in[7];
    const float* bv    = (const float*)d_in[8];
    const float* Wo    = (const float*)d_in[9];
    const float* bo    = (const float*)d_in[10];
    const float* s1    = (const float*)d_in[11];
    const float* b1    = (const float*)d_in[12];
    const float* s2    = (const float*)d_in[13];
    const float* b2l   = (const float*)d_in[14];
    const float* W1    = (const float*)d_in[15];
    const float* b1f   = (const float*)d_in[16];
    const float* W2    = (const float*)d_in[17];
    const float* b2o   = (const float*)d_in[18];
    float* out = (float*)d_out;

    fused_kernel<<<NB, NT>>>(x, mask, token, Wq, bq, Wk, Wv, bv, Wo, bo,
                             s1, b1, s2, b2l, W1, b1f, W2, b2o, out);
}